// round 14
// baseline (speedup 1.0000x reference)
#include <cuda_runtime.h>
#include <cstdint>

// ---------------------------------------------------------------------------
// EmbedderMessageFunction (TGN message): fused gather + time-encode +
// MLP(512 -> relu 512 -> 256), TF32 mma.sync (m16n8k8), M-tile = 64 events.
// R14: R13 + B prefetch distance 4 (four live B fragment arrays, ks+=4 loop)
//      to cover the ~250-cycle L2 latency on weight loads.
// ---------------------------------------------------------------------------

#define E_TILE   64
#define THREADS  256

// smem layout (bytes)
#define OFF_A     0            // A fragment region: 4 mt * 64 ks * 32 lanes * 16B
#define OFF_SA    131072       // staging A: 64 x 136 floats = 34816
#define OFF_SB    165888       // staging B: 64 x 136 floats = 34816
#define OFF_B1    200704       // 512 floats
#define OFF_B2    202752       // 256 floats
#define OFF_FREQ  203776       // 128 floats
#define OFF_PHASE 204288       // 128 floats
#define OFF_DT    204800       // 64 floats
#define OFF_SRC   205056       // 64 ints
#define OFF_DST   205312
#define OFF_EID   205568
#define SMEM_BYTES 205824

#define STAG_PITCH 136         // floats; 544B rows keep 16B cp.async alignment

// fragment-major tf32 weights (built once per launch by prep kernel)
// W1F: [ntg 0..63][ks 0..63][lane 0..31][2]   (HIDDEN=512 -> 64 n-tiles)
// W2F: [ntg 0..31][ks 0..63][lane 0..31][2]   (OUT=256    -> 32 n-tiles)
__device__ float g_W1F[64 * 64 * 32 * 2];
__device__ float g_W2F[32 * 64 * 32 * 2];

static __device__ __forceinline__ uint32_t f2tf32(float x) {
    uint32_t r;
    asm("cvt.rna.tf32.f32 %0, %1;" : "=r"(r) : "f"(x));
    return r;
}

static __device__ __forceinline__ uint32_t smem_u32(const void* p) {
    uint32_t a;
    asm("{ .reg .u64 t; cvta.to.shared.u64 t, %1; cvt.u32.u64 %0, t; }"
        : "=r"(a) : "l"(p));
    return a;
}

static __device__ __forceinline__ void cp16(uint32_t dst, const void* src) {
    asm volatile("cp.async.cg.shared.global [%0], [%1], 16;"
                 :: "r"(dst), "l"(src) : "memory");
}
#define CP_COMMIT() asm volatile("cp.async.commit_group;" ::: "memory")
#define CP_WAIT(n)  asm volatile("cp.async.wait_group %0;" :: "n"(n) : "memory")

static __device__ __forceinline__ void mma8(float* d, uint4 a, float2 b) {
    asm volatile(
        "mma.sync.aligned.m16n8k8.row.col.f32.tf32.tf32.f32 "
        "{%0,%1,%2,%3}, {%4,%5,%6,%7}, {%8,%9}, {%0,%1,%2,%3};"
        : "+f"(d[0]), "+f"(d[1]), "+f"(d[2]), "+f"(d[3])
        : "r"(a.x), "r"(a.y), "r"(a.z), "r"(a.w),
          "r"(__float_as_uint(b.x)), "r"(__float_as_uint(b.y)));
}

// ---------------------------- prep kernel ----------------------------------
// B fragment layout for mma.m16n8k8.row.col:
//   b0: (row = lane%4,     col = lane/4)  of the 8x8 k-by-n tile
//   b1: (row = lane%4 + 4, col = lane/4)

__global__ void prep_weights_kernel(const float* __restrict__ W1,
                                    const float* __restrict__ W2) {
    int t0 = blockIdx.x * blockDim.x + threadIdx.x;
    int stride = gridDim.x * blockDim.x;
    for (int t = t0; t < 64 * 64 * 32; t += stride) {
        int lane = t & 31, ks = (t >> 5) & 63, ntg = t >> 11;
        int r = lane & 3, cg = lane >> 2;
        int k0 = ks * 8, n = ntg * 8 + cg;
        g_W1F[2 * t]     = __uint_as_float(f2tf32(W1[(size_t)(k0 + r) * 512 + n]));
        g_W1F[2 * t + 1] = __uint_as_float(f2tf32(W1[(size_t)(k0 + r + 4) * 512 + n]));
    }
    for (int t = t0; t < 32 * 64 * 32; t += stride) {
        int lane = t & 31, ks = (t >> 5) & 63, ntg = t >> 11;
        int r = lane & 3, cg = lane >> 2;
        int k0 = ks * 8, n = ntg * 8 + cg;
        g_W2F[2 * t]     = __uint_as_float(f2tf32(W2[(size_t)(k0 + r) * 256 + n]));
        g_W2F[2 * t + 1] = __uint_as_float(f2tf32(W2[(size_t)(k0 + r + 4) * 256 + n]));
    }
}

// ----------------------------- main kernel ---------------------------------

__global__ __launch_bounds__(THREADS, 1)
void tgn_msg_kernel(const int*   __restrict__ src_nodes,
                    const int*   __restrict__ dst_nodes,
                    const float* __restrict__ timestamps,
                    const int*   __restrict__ event_indices,
                    const int*   __restrict__ nidx,
                    const float* __restrict__ node_emb,
                    const float* __restrict__ last_update,
                    const float* __restrict__ feats,
                    const float* __restrict__ freq,
                    const float* __restrict__ phase,
                    const float* __restrict__ b1,
                    const float* __restrict__ b2,
                    float*       __restrict__ out,
                    int E) {
    extern __shared__ char smem[];
    float* sA    = (float*)(smem + OFF_A);
    float* stagA = (float*)(smem + OFF_SA);
    float* stagB = (float*)(smem + OFF_SB);
    float* s_b1  = (float*)(smem + OFF_B1);
    float* s_b2  = (float*)(smem + OFF_B2);
    float* s_frq = (float*)(smem + OFF_FREQ);
    float* s_phs = (float*)(smem + OFF_PHASE);
    float* s_dt  = (float*)(smem + OFF_DT);
    int*   s_src = (int*)(smem + OFF_SRC);
    int*   s_dst = (int*)(smem + OFF_DST);
    int*   s_eid = (int*)(smem + OFF_EID);

    const uint32_t sbA = smem_u32(stagA);
    const uint32_t sbB = smem_u32(stagB);

    const int tid  = threadIdx.x;
    const int warp = tid >> 5;
    const int lane = tid & 31;
    const int gid  = lane >> 2;   // group id (row within fragment)
    const int tig  = lane & 3;    // thread in group

    const int base = blockIdx.x * E_TILE;

    // ---- preamble: indices / scalars into smem ----
    if (tid < E_TILE) {
        int e = base + tid;
        if (e >= E) e = E - 1;
        s_src[tid] = src_nodes[e];
        s_dst[tid] = dst_nodes[e];
        s_eid[tid] = event_indices[e];
        s_dt[tid]  = timestamps[e] - last_update[nidx[e]];
    }
    if (tid < 128) { s_frq[tid] = freq[tid]; s_phs[tid] = phase[tid]; }
    for (int i = tid; i < 512; i += THREADS) s_b1[i] = b1[i];
    if (tid < 256) s_b2[tid] = b2[tid];
    __syncthreads();

    // ---- async gather issue: src -> stagA (G0), dst -> stagB (G1) ----
    #pragma unroll
    for (int i = 0; i < 8; i++) {
        int lin = i * 256 + tid;
        int row = lin >> 5;
        int q   = lin & 31;
        cp16(sbA + (row * STAG_PITCH + q * 4) * 4,
             node_emb + (size_t)s_src[row] * 128 + q * 4);
    }
    CP_COMMIT();   // G0
    #pragma unroll
    for (int i = 0; i < 8; i++) {
        int lin = i * 256 + tid;
        int row = lin >> 5;
        int q   = lin & 31;
        cp16(sbB + (row * STAG_PITCH + q * 4) * 4,
             node_emb + (size_t)s_dst[row] * 128 + q * 4);
    }
    CP_COMMIT();   // G1

    // ---- chunk 2 (time encoding): compute cos directly in fragment layout ----
    #pragma unroll
    for (int i = 0; i < 8; i++) {
        int f   = i * 8 + warp;
        int mt  = f >> 4;
        int ksl = f & 15;
        int ra = mt * 16 + gid;
        int ca = ksl * 8 + tig;
        float dt0 = s_dt[ra], dt1 = s_dt[ra + 8];
        float f0 = s_frq[ca], f4 = s_frq[ca + 4];
        float p0 = s_phs[ca], p4 = s_phs[ca + 4];
        uint4 u;
        u.x = f2tf32(cosf(__fmaf_rn(dt0, f0, p0)));
        u.y = f2tf32(cosf(__fmaf_rn(dt1, f0, p0)));
        u.z = f2tf32(cosf(__fmaf_rn(dt0, f4, p4)));
        u.w = f2tf32(cosf(__fmaf_rn(dt1, f4, p4)));
        *(uint4*)(sA + ((mt * 64 + 32 + ksl) * 32 + lane) * 4) = u;
    }

    // ---- repack helper (reads staging, rounds to tf32, writes fragments) ----
    auto repack = [&](float* stag, int chunk) {
        #pragma unroll
        for (int i = 0; i < 8; i++) {
            int f   = i * 8 + warp;
            int mt  = f >> 4;
            int ksl = f & 15;
            int ra = mt * 16 + gid;
            int ca = ksl * 8 + tig;
            uint4 u;
            u.x = f2tf32(stag[ra * STAG_PITCH + ca]);
            u.y = f2tf32(stag[(ra + 8) * STAG_PITCH + ca]);
            u.z = f2tf32(stag[ra * STAG_PITCH + ca + 4]);
            u.w = f2tf32(stag[(ra + 8) * STAG_PITCH + ca + 4]);
            *(uint4*)(sA + ((mt * 64 + chunk * 16 + ksl) * 32 + lane) * 4) = u;
        }
    };

    CP_WAIT(1);          // G0 (src) landed
    __syncthreads();
    repack(stagA, 0);    // src -> chunk 0
    __syncthreads();     // stagA free

    // ---- feats -> stagA (G2) ----
    #pragma unroll
    for (int i = 0; i < 8; i++) {
        int lin = i * 256 + tid;
        int row = lin >> 5;
        int q   = lin & 31;
        cp16(sbA + (row * STAG_PITCH + q * 4) * 4,
             feats + (size_t)s_eid[row] * 128 + q * 4);
    }
    CP_COMMIT();   // G2

    CP_WAIT(1);          // G1 (dst) landed (G2 may be pending)
    __syncthreads();
    repack(stagB, 1);    // dst -> chunk 1

    CP_WAIT(0);          // G2 (feats) landed
    __syncthreads();
    repack(stagA, 3);    // feats -> chunk 3
    __syncthreads();

    // ---- GEMM1: h[64x512] = msg @ W1 ; N-slice 64 per warp ----
    // Distance-4 copy-free B buffer: four live arrays, each reloaded right
    // after use for ks+4..ks+7. Single a[4] reused across all four halves.
    float acc[4][8][4];
    #pragma unroll
    for (int mt = 0; mt < 4; mt++)
        #pragma unroll
        for (int nt = 0; nt < 8; nt++)
            #pragma unroll
            for (int r = 0; r < 4; r++) acc[mt][nt][r] = 0.0f;

    {
        const float* bbase = g_W1F + (size_t)(warp * 8) * 4096;
        float2 bq0[8], bq1[8], bq2[8], bq3[8];
        #pragma unroll
        for (int nt = 0; nt < 8; nt++) {
            bq0[nt] = *(const float2*)(bbase + (nt * 64 + 0) * 64 + lane * 2);
            bq1[nt] = *(const float2*)(bbase + (nt * 64 + 1) * 64 + lane * 2);
            bq2[nt] = *(const float2*)(bbase + (nt * 64 + 2) * 64 + lane * 2);
            bq3[nt] = *(const float2*)(bbase + (nt * 64 + 3) * 64 + lane * 2);
        }
        #pragma unroll 1
        for (int ks = 0; ks < 64; ks += 4) {
            uint4 a[4];
            // half 0
            #pragma unroll
            for (int mt = 0; mt < 4; mt++)
                a[mt] = *(const uint4*)(sA + ((mt * 64 + ks) * 32 + lane) * 4);
            #pragma unroll
            for (int mt = 0; mt < 4; mt++)
                #pragma unroll
                for (int nt = 0; nt < 8; nt++)
                    mma8(acc[mt][nt], a[mt], bq0[nt]);
            if (ks < 60) {
                #pragma unroll
                for (int nt = 0; nt < 8; nt++)
                    bq0[nt] = *(const float2*)(bbase + (nt * 64 + ks + 4) * 64 + lane * 2);
            }
            // half 1
            #pragma unroll
            for (int mt = 0; mt < 4; mt++)
                a[mt] = *(const uint4*)(sA + ((mt * 64 + ks + 1) * 32 + lane) * 4);
            #pragma unroll
            for (int mt = 0; mt < 4; mt++)
                #pragma unroll
                for (int nt = 0; nt < 8; nt++)
                    mma8(acc[mt][nt], a[mt], bq1[nt]);
            if (ks < 60) {
                #pragma unroll
                for (int nt = 0; nt < 8; nt++)
                    bq1[nt] = *(const float2*)(bbase + (nt * 64 + ks + 5) * 64 + lane * 2);
            }
            // half 2
            #pragma unroll
            for (int mt = 0; mt < 4; mt++)
                a[mt] = *(const uint4*)(sA + ((mt * 64 + ks + 2) * 32 + lane) * 4);
            #pragma unroll
            for (int mt = 0; mt < 4; mt++)
                #pragma unroll
                for (int nt = 0; nt < 8; nt++)
                    mma8(acc[mt][nt], a[mt], bq2[nt]);
            if (ks < 60) {
                #pragma unroll
                for (int nt = 0; nt < 8; nt++)
                    bq2[nt] = *(const float2*)(bbase + (nt * 64 + ks + 6) * 64 + lane * 2);
            }
            // half 3
            #pragma unroll
            for (int mt = 0; mt < 4; mt++)
                a[mt] = *(const uint4*)(sA + ((mt * 64 + ks + 3) * 32 + lane) * 4);
            #pragma unroll
            for (int mt = 0; mt < 4; mt++)
                #pragma unroll
                for (int nt = 0; nt < 8; nt++)
                    mma8(acc[mt][nt], a[mt], bq3[nt]);
            if (ks < 60) {
                #pragma unroll
                for (int nt = 0; nt < 8; nt++)
                    bq3[nt] = *(const float2*)(bbase + (nt * 64 + ks + 7) * 64 + lane * 2);
            }
        }
    }

    // ---- relu + b1, write h back into A region (fragment-major) ----
    __syncthreads();   // everyone done reading msg A
    #pragma unroll
    for (int mt = 0; mt < 4; mt++) {
        #pragma unroll
        for (int nt = 0; nt < 8; nt++) {
            #pragma unroll
            for (int cr = 0; cr < 4; cr++) {
                int row = mt * 16 + gid + 8 * (cr >> 1);
                int n   = warp * 64 + nt * 8 + 2 * tig + (cr & 1);
                float v = fmaxf(acc[mt][nt][cr] + s_b1[n], 0.0f);
                int r15 = row & 15;
                int ks  = n >> 3;
                int c0  = n & 7;
                int l2  = (r15 & 7) * 4 + (c0 & 3);
                int rg  = (r15 >> 3) + 2 * (c0 >> 2);
                sA[((mt * 64 + ks) * 32 + l2) * 4 + rg] =
                    __uint_as_float(f2tf32(v));
            }
        }
    }
    __syncthreads();

    // ---- GEMM2: out[64x256] = h @ W2 ; N-slice 32 per warp (distance-4) ----
    float acc2[4][4][4];
    #pragma unroll
    for (int mt = 0; mt < 4; mt++)
        #pragma unroll
        for (int nt = 0; nt < 4; nt++)
            #pragma unroll
            for (int r = 0; r < 4; r++) acc2[mt][nt][r] = 0.0f;

    {
        const float* bbase = g_W2F + (size_t)(warp * 4) * 4096;
        float2 bq0[4], bq1[4], bq2[4], bq3[4];
        #pragma unroll
        for (int nt = 0; nt < 4; nt++) {
            bq0[nt] = *(const float2*)(bbase + (nt * 64 + 0) * 64 + lane * 2);
            bq1[nt] = *(const float2*)(bbase + (nt * 64 + 1) * 64 + lane * 2);
            bq2[nt] = *(const float2*)(bbase + (nt * 64 + 2) * 64 + lane * 2);
            bq3[nt] = *(const float2*)(bbase + (nt * 64 + 3) * 64 + lane * 2);
        }
        #pragma unroll 1
        for (int ks = 0; ks < 64; ks += 4) {
            uint4 a[4];
            // half 0
            #pragma unroll
            for (int mt = 0; mt < 4; mt++)
                a[mt] = *(const uint4*)(sA + ((mt * 64 + ks) * 32 + lane) * 4);
            #pragma unroll
            for (int mt = 0; mt < 4; mt++)
                #pragma unroll
                for (int nt = 0; nt < 4; nt++)
                    mma8(acc2[mt][nt], a[mt], bq0[nt]);
            if (ks < 60) {
                #pragma unroll
                for (int nt = 0; nt < 4; nt++)
                    bq0[nt] = *(const float2*)(bbase + (nt * 64 + ks + 4) * 64 + lane * 2);
            }
            // half 1
            #pragma unroll
            for (int mt = 0; mt < 4; mt++)
                a[mt] = *(const uint4*)(sA + ((mt * 64 + ks + 1) * 32 + lane) * 4);
            #pragma unroll
            for (int mt = 0; mt < 4; mt++)
                #pragma unroll
                for (int nt = 0; nt < 4; nt++)
                    mma8(acc2[mt][nt], a[mt], bq1[nt]);
            if (ks < 60) {
                #pragma unroll
                for (int nt = 0; nt < 4; nt++)
                    bq1[nt] = *(const float2*)(bbase + (nt * 64 + ks + 5) * 64 + lane * 2);
            }
            // half 2
            #pragma unroll
            for (int mt = 0; mt < 4; mt++)
                a[mt] = *(const uint4*)(sA + ((mt * 64 + ks + 2) * 32 + lane) * 4);
            #pragma unroll
            for (int mt = 0; mt < 4; mt++)
                #pragma unroll
                for (int nt = 0; nt < 4; nt++)
                    mma8(acc2[mt][nt], a[mt], bq2[nt]);
            if (ks < 60) {
                #pragma unroll
                for (int nt = 0; nt < 4; nt++)
                    bq2[nt] = *(const float2*)(bbase + (nt * 64 + ks + 6) * 64 + lane * 2);
            }
            // half 3
            #pragma unroll
            for (int mt = 0; mt < 4; mt++)
                a[mt] = *(const uint4*)(sA + ((mt * 64 + ks + 3) * 32 + lane) * 4);
            #pragma unroll
            for (int mt = 0; mt < 4; mt++)
                #pragma unroll
                for (int nt = 0; nt < 4; nt++)
                    mma8(acc2[mt][nt], a[mt], bq3[nt]);
            if (ks < 60) {
                #pragma unroll
                for (int nt = 0; nt < 4; nt++)
                    bq3[nt] = *(const float2*)(bbase + (nt * 64 + ks + 7) * 64 + lane * 2);
            }
        }
    }

    // ---- epilogue: + b2, store ----
    #pragma unroll
    for (int mt = 0; mt < 4; mt++) {
        #pragma unroll
        for (int nt = 0; nt < 4; nt++) {
            int n  = warp * 32 + nt * 8 + 2 * tig;
            float bx = s_b2[n], by = s_b2[n + 1];
            int r0 = mt * 16 + gid;
            int e0 = base + r0;
            if (e0 < E) {
                float2 o;
                o.x = acc2[mt][nt][0] + bx;
                o.y = acc2[mt][nt][1] + by;
                *(float2*)(out + (size_t)e0 * 256 + n) = o;
            }
            int e1 = base + r0 + 8;
            if (e1 < E) {
                float2 o;
                o.x = acc2[mt][nt][2] + bx;
                o.y = acc2[mt][nt][3] + by;
                *(float2*)(out + (size_t)e1 * 256 + n) = o;
            }
        }
    }
}

// ------------------------------- launch ------------------------------------

extern "C" void kernel_launch(void* const* d_in, const int* in_sizes, int n_in,
                              void* d_out, int out_size) {
    const int*   src_nodes     = (const int*)d_in[0];
    const int*   dst_nodes     = (const int*)d_in[1];
    const float* timestamps    = (const float*)d_in[2];
    const int*   event_indices = (const int*)d_in[3];
    const int*   nidx          = (const int*)d_in[4];
    const float* node_emb      = (const float*)d_in[5];
    const float* last_update   = (const float*)d_in[6];
    const float* feats         = (const float*)d_in[7];
    const float* freq          = (const float*)d_in[8];
    const float* phase         = (const float*)d_in[9];
    const float* W1            = (const float*)d_in[10];
    const float* b1v           = (const float*)d_in[11];
    const float* W2            = (const float*)d_in[12];
    const float* b2v           = (const float*)d_in[13];
    float* out = (float*)d_out;

    int E = in_sizes[0];

    cudaFuncSetAttribute(tgn_msg_kernel,
                         cudaFuncAttributeMaxDynamicSharedMemorySize, SMEM_BYTES);

    prep_weights_kernel<<<128, 256>>>(W1, W2);

    int nblk = (E + E_TILE - 1) / E_TILE;
    tgn_msg_kernel<<<nblk, THREADS, SMEM_BYTES>>>(
        src_nodes, dst_nodes, timestamps, event_indices, nidx,
        node_emb, last_update, feats, freq, phase, b1v, b2v, out, E);
}

// round 15
// speedup vs baseline: 1.8537x; 1.8537x over previous
#include <cuda_runtime.h>
#include <cuda_fp16.h>
#include <cstdint>

// ---------------------------------------------------------------------------
// EmbedderMessageFunction (TGN message): fused gather + time-encode +
// MLP(512 -> relu 512 -> 256), FP16 mma.sync (m16n8k16, fp32 accum),
// M-tile = 64 events. R15: R13 structure moved from tf32/k8 to fp16/k16
// (2x tensor MAC rate, same 10-bit mantissa as tf32).
// ---------------------------------------------------------------------------

#define E_TILE   64
#define THREADS  256

// smem layout (bytes)
#define OFF_A     0            // A fp16 fragments: 4 mt * 32 ks * 32 lanes * 16B = 65536
#define OFF_SA    65536        // staging A: 64 x 136 fp32 = 34816
#define OFF_SB    100352       // staging B: 64 x 136 fp32 = 34816
#define OFF_B1    135168       // 512 floats
#define OFF_B2    137216       // 256 floats
#define OFF_FREQ  138240       // 128 floats
#define OFF_PHASE 138752       // 128 floats
#define OFF_DT    139264       // 64 floats
#define OFF_SRC   139520       // 64 ints
#define OFF_DST   139776
#define OFF_EID   140032
#define SMEM_BYTES 140288

#define STAG_PITCH 136         // floats; 544B rows keep 16B cp.async alignment

// fp16x2-packed B-fragment weights (built once per launch by prep kernel).
// W1H: [ntg 0..63][ks16 0..31][lane 0..31][2] uint32   (HIDDEN=512)
// W2H: [ntg 0..31][ks16 0..31][lane 0..31][2] uint32   (OUT=256)
__device__ uint32_t g_W1H[64 * 32 * 32 * 2];
__device__ uint32_t g_W2H[32 * 32 * 32 * 2];

// pack two fp32 -> fp16x2 (lo in low 16 bits)
static __device__ __forceinline__ uint32_t packh2(float lo, float hi) {
    uint32_t r;
    asm("cvt.rn.f16x2.f32 %0, %1, %2;" : "=r"(r) : "f"(hi), "f"(lo));
    return r;
}

static __device__ __forceinline__ uint32_t smem_u32(const void* p) {
    uint32_t a;
    asm("{ .reg .u64 t; cvta.to.shared.u64 t, %1; cvt.u32.u64 %0, t; }"
        : "=r"(a) : "l"(p));
    return a;
}

static __device__ __forceinline__ void cp16(uint32_t dst, const void* src) {
    asm volatile("cp.async.cg.shared.global [%0], [%1], 16;"
                 :: "r"(dst), "l"(src) : "memory");
}
#define CP_COMMIT() asm volatile("cp.async.commit_group;" ::: "memory")
#define CP_WAIT(n)  asm volatile("cp.async.wait_group %0;" :: "n"(n) : "memory")

static __device__ __forceinline__ void mma16(float* d, uint4 a, uint2 b) {
    asm volatile(
        "mma.sync.aligned.m16n8k16.row.col.f32.f16.f16.f32 "
        "{%0,%1,%2,%3}, {%4,%5,%6,%7}, {%8,%9}, {%0,%1,%2,%3};"
        : "+f"(d[0]), "+f"(d[1]), "+f"(d[2]), "+f"(d[3])
        : "r"(a.x), "r"(a.y), "r"(a.z), "r"(a.w),
          "r"(b.x), "r"(b.y));
}

// ---------------------------- prep kernel ----------------------------------
// B fragment layout for mma.m16n8k16.row.col (fp16):
//   b0 = fp16x2{ W[k0+2tig][n], W[k0+2tig+1][n] }
//   b1 = fp16x2{ W[k0+8+2tig][n], W[k0+9+2tig][n] }   (n = ntg*8 + lane/4)

__global__ void prep_weights_kernel(const float* __restrict__ W1,
                                    const float* __restrict__ W2) {
    int t0 = blockIdx.x * blockDim.x + threadIdx.x;
    int stride = gridDim.x * blockDim.x;
    for (int t = t0; t < 64 * 32 * 32; t += stride) {
        int lane = t & 31, ks = (t >> 5) & 31, ntg = t >> 10;
        int tig = lane & 3, cg = lane >> 2;
        int k0 = ks * 16, n = ntg * 8 + cg;
        g_W1H[2 * t]     = packh2(W1[(size_t)(k0 + 2 * tig) * 512 + n],
                                  W1[(size_t)(k0 + 2 * tig + 1) * 512 + n]);
        g_W1H[2 * t + 1] = packh2(W1[(size_t)(k0 + 8 + 2 * tig) * 512 + n],
                                  W1[(size_t)(k0 + 9 + 2 * tig) * 512 + n]);
    }
    for (int t = t0; t < 32 * 32 * 32; t += stride) {
        int lane = t & 31, ks = (t >> 5) & 31, ntg = t >> 10;
        int tig = lane & 3, cg = lane >> 2;
        int k0 = ks * 16, n = ntg * 8 + cg;
        g_W2H[2 * t]     = packh2(W2[(size_t)(k0 + 2 * tig) * 256 + n],
                                  W2[(size_t)(k0 + 2 * tig + 1) * 256 + n]);
        g_W2H[2 * t + 1] = packh2(W2[(size_t)(k0 + 8 + 2 * tig) * 256 + n],
                                  W2[(size_t)(k0 + 9 + 2 * tig) * 256 + n]);
    }
}

// ----------------------------- main kernel ---------------------------------

__global__ __launch_bounds__(THREADS, 1)
void tgn_msg_kernel(const int*   __restrict__ src_nodes,
                    const int*   __restrict__ dst_nodes,
                    const float* __restrict__ timestamps,
                    const int*   __restrict__ event_indices,
                    const int*   __restrict__ nidx,
                    const float* __restrict__ node_emb,
                    const float* __restrict__ last_update,
                    const float* __restrict__ feats,
                    const float* __restrict__ freq,
                    const float* __restrict__ phase,
                    const float* __restrict__ b1,
                    const float* __restrict__ b2,
                    float*       __restrict__ out,
                    int E) {
    extern __shared__ char smem[];
    uint32_t* sA  = (uint32_t*)(smem + OFF_A);   // fp16x2 words
    float* stagA  = (float*)(smem + OFF_SA);
    float* stagB  = (float*)(smem + OFF_SB);
    float* s_b1   = (float*)(smem + OFF_B1);
    float* s_b2   = (float*)(smem + OFF_B2);
    float* s_frq  = (float*)(smem + OFF_FREQ);
    float* s_phs  = (float*)(smem + OFF_PHASE);
    float* s_dt   = (float*)(smem + OFF_DT);
    int*   s_src  = (int*)(smem + OFF_SRC);
    int*   s_dst  = (int*)(smem + OFF_DST);
    int*   s_eid  = (int*)(smem + OFF_EID);

    const uint32_t sbA = smem_u32(stagA);
    const uint32_t sbB = smem_u32(stagB);

    const int tid  = threadIdx.x;
    const int warp = tid >> 5;
    const int lane = tid & 31;
    const int gid  = lane >> 2;   // group id (row within fragment)
    const int tig  = lane & 3;    // thread in group

    const int base = blockIdx.x * E_TILE;

    // ---- preamble: indices / scalars into smem ----
    if (tid < E_TILE) {
        int e = base + tid;
        if (e >= E) e = E - 1;
        s_src[tid] = src_nodes[e];
        s_dst[tid] = dst_nodes[e];
        s_eid[tid] = event_indices[e];
        s_dt[tid]  = timestamps[e] - last_update[nidx[e]];
    }
    if (tid < 128) { s_frq[tid] = freq[tid]; s_phs[tid] = phase[tid]; }
    for (int i = tid; i < 512; i += THREADS) s_b1[i] = b1[i];
    if (tid < 256) s_b2[tid] = b2[tid];
    __syncthreads();

    // ---- async gather issue: src -> stagA (G0), dst -> stagB (G1) ----
    #pragma unroll
    for (int i = 0; i < 8; i++) {
        int lin = i * 256 + tid;
        int row = lin >> 5;
        int q   = lin & 31;
        cp16(sbA + (row * STAG_PITCH + q * 4) * 4,
             node_emb + (size_t)s_src[row] * 128 + q * 4);
    }
    CP_COMMIT();   // G0
    #pragma unroll
    for (int i = 0; i < 8; i++) {
        int lin = i * 256 + tid;
        int row = lin >> 5;
        int q   = lin & 31;
        cp16(sbB + (row * STAG_PITCH + q * 4) * 4,
             node_emb + (size_t)s_dst[row] * 128 + q * 4);
    }
    CP_COMMIT();   // G1

    // ---- chunk 2 (time encoding): cos directly into fp16 A fragments ----
    // chunk 2 covers k-steps 16..23 (cols 256..383 of msg).
    #pragma unroll
    for (int i = 0; i < 4; i++) {
        int f   = i * 8 + warp;       // fragment 0..31 of this chunk
        int mt  = f >> 3;             // m-tile 0..3
        int ksl = f & 7;              // local kstep16 0..7
        int ra = mt * 16 + gid;
        int ca = ksl * 16 + 2 * tig;  // time-dim col 0..127
        float dt0 = s_dt[ra], dt1 = s_dt[ra + 8];
        uint4 u;
        u.x = packh2(cosf(__fmaf_rn(dt0, s_frq[ca],     s_phs[ca])),
                     cosf(__fmaf_rn(dt0, s_frq[ca + 1], s_phs[ca + 1])));
        u.y = packh2(cosf(__fmaf_rn(dt1, s_frq[ca],     s_phs[ca])),
                     cosf(__fmaf_rn(dt1, s_frq[ca + 1], s_phs[ca + 1])));
        u.z = packh2(cosf(__fmaf_rn(dt0, s_frq[ca + 8], s_phs[ca + 8])),
                     cosf(__fmaf_rn(dt0, s_frq[ca + 9], s_phs[ca + 9])));
        u.w = packh2(cosf(__fmaf_rn(dt1, s_frq[ca + 8], s_phs[ca + 8])),
                     cosf(__fmaf_rn(dt1, s_frq[ca + 9], s_phs[ca + 9])));
        *(uint4*)(sA + ((mt * 32 + 16 + ksl) * 32 + lane) * 4) = u;
    }

    // ---- repack helper: staging fp32 -> fp16 A fragments for one chunk ----
    auto repack = [&](float* stag, int chunk) {
        #pragma unroll
        for (int i = 0; i < 4; i++) {
            int f   = i * 8 + warp;
            int mt  = f >> 3;
            int ksl = f & 7;
            int ra = mt * 16 + gid;
            int ca = ksl * 16 + 2 * tig;
            uint4 u;
            u.x = packh2(stag[ra * STAG_PITCH + ca],
                         stag[ra * STAG_PITCH + ca + 1]);
            u.y = packh2(stag[(ra + 8) * STAG_PITCH + ca],
                         stag[(ra + 8) * STAG_PITCH + ca + 1]);
            u.z = packh2(stag[ra * STAG_PITCH + ca + 8],
                         stag[ra * STAG_PITCH + ca + 9]);
            u.w = packh2(stag[(ra + 8) * STAG_PITCH + ca + 8],
                         stag[(ra + 8) * STAG_PITCH + ca + 9]);
            *(uint4*)(sA + ((mt * 32 + chunk * 8 + ksl) * 32 + lane) * 4) = u;
        }
    };

    CP_WAIT(1);          // G0 (src) landed
    __syncthreads();
    repack(stagA, 0);    // src -> k-steps 0..7
    __syncthreads();     // stagA free

    // ---- feats -> stagA (G2) ----
    #pragma unroll
    for (int i = 0; i < 8; i++) {
        int lin = i * 256 + tid;
        int row = lin >> 5;
        int q   = lin & 31;
        cp16(sbA + (row * STAG_PITCH + q * 4) * 4,
             feats + (size_t)s_eid[row] * 128 + q * 4);
    }
    CP_COMMIT();   // G2

    CP_WAIT(1);          // G1 (dst) landed (G2 may be pending)
    __syncthreads();
    repack(stagB, 1);    // dst -> k-steps 8..15

    CP_WAIT(0);          // G2 (feats) landed
    __syncthreads();
    repack(stagA, 3);    // feats -> k-steps 24..31
    __syncthreads();

    // ---- GEMM1: h[64x512] = msg @ W1 ; N-slice 64 per warp, 32 k16-steps ----
    float acc[4][8][4];
    #pragma unroll
    for (int mt = 0; mt < 4; mt++)
        #pragma unroll
        for (int nt = 0; nt < 8; nt++)
            #pragma unroll
            for (int r = 0; r < 4; r++) acc[mt][nt][r] = 0.0f;

    {
        const uint32_t* bbase = g_W1H + (size_t)(warp * 8) * 2048; // 8 ntg * 32 ks * 64
        uint2 b0[8], b1f[8];
        #pragma unroll
        for (int nt = 0; nt < 8; nt++) {
            b0[nt]  = *(const uint2*)(bbase + ((nt * 32 + 0) * 32 + lane) * 2);
            b1f[nt] = *(const uint2*)(bbase + ((nt * 32 + 1) * 32 + lane) * 2);
        }
        #pragma unroll 1
        for (int ks = 0; ks < 32; ks += 2) {
            uint4 a[4];
            // even half
            #pragma unroll
            for (int mt = 0; mt < 4; mt++)
                a[mt] = *(const uint4*)(sA + ((mt * 32 + ks) * 32 + lane) * 4);
            #pragma unroll
            for (int mt = 0; mt < 4; mt++)
                #pragma unroll
                for (int nt = 0; nt < 8; nt++)
                    mma16(acc[mt][nt], a[mt], b0[nt]);
            if (ks < 30) {
                #pragma unroll
                for (int nt = 0; nt < 8; nt++)
                    b0[nt] = *(const uint2*)(bbase + ((nt * 32 + ks + 2) * 32 + lane) * 2);
            }
            // odd half (reuse a)
            #pragma unroll
            for (int mt = 0; mt < 4; mt++)
                a[mt] = *(const uint4*)(sA + ((mt * 32 + ks + 1) * 32 + lane) * 4);
            #pragma unroll
            for (int mt = 0; mt < 4; mt++)
                #pragma unroll
                for (int nt = 0; nt < 8; nt++)
                    mma16(acc[mt][nt], a[mt], b1f[nt]);
            if (ks < 30) {
                #pragma unroll
                for (int nt = 0; nt < 8; nt++)
                    b1f[nt] = *(const uint2*)(bbase + ((nt * 32 + ks + 3) * 32 + lane) * 2);
            }
        }
    }

    // ---- relu + b1: write h as fp16 A fragments for GEMM2 (in place) ----
    // h col n -> GEMM2 kstep ks2 = n>>4; writer lane owns its own fragment
    // slot: word index reg = rowhalf + 2*(nt&1), ks2 = warp*4 + (nt>>1).
    __syncthreads();   // everyone done reading msg A
    #pragma unroll
    for (int mt = 0; mt < 4; mt++) {
        #pragma unroll
        for (int nt = 0; nt < 8; nt++) {
            int n_even = warp * 64 + nt * 8 + 2 * tig;
            int ks2 = warp * 4 + (nt >> 1);
            uint32_t* dst = sA + ((mt * 32 + ks2) * 32 + lane) * 4 + 2 * (nt & 1);
            float v0 = fmaxf(acc[mt][nt][0] + s_b1[n_even],     0.0f);
            float v1 = fmaxf(acc[mt][nt][1] + s_b1[n_even + 1], 0.0f);
            float v2 = fmaxf(acc[mt][nt][2] + s_b1[n_even],     0.0f);
            float v3 = fmaxf(acc[mt][nt][3] + s_b1[n_even + 1], 0.0f);
            dst[0] = packh2(v0, v1);   // row gid
            dst[1] = packh2(v2, v3);   // row gid+8
        }
    }
    __syncthreads();

    // ---- GEMM2: out[64x256] = h @ W2 ; N-slice 32 per warp, 32 k16-steps ----
    float acc2[4][4][4];
    #pragma unroll
    for (int mt = 0; mt < 4; mt++)
        #pragma unroll
        for (int nt = 0; nt < 4; nt++)
            #pragma unroll
            for (int r = 0; r < 4; r++) acc2[mt][nt][r] = 0.0f;

    {
        const uint32_t* bbase = g_W2H + (size_t)(warp * 4) * 2048;
        uint2 b0[4], b1f[4];
        #pragma unroll
        for (int nt = 0; nt < 4; nt++) {
            b0[nt]  = *(const uint2*)(bbase + ((nt * 32 + 0) * 32 + lane) * 2);
            b1f[nt] = *(const uint2*)(bbase + ((nt * 32 + 1) * 32 + lane) * 2);
        }
        #pragma unroll 1
        for (int ks = 0; ks < 32; ks += 2) {
            uint4 a[4];
            // even half
            #pragma unroll
            for (int mt = 0; mt < 4; mt++)
                a[mt] = *(const uint4*)(sA + ((mt * 32 + ks) * 32 + lane) * 4);
            #pragma unroll
            for (int mt = 0; mt < 4; mt++)
                #pragma unroll
                for (int nt = 0; nt < 4; nt++)
                    mma16(acc2[mt][nt], a[mt], b0[nt]);
            if (ks < 30) {
                #pragma unroll
                for (int nt = 0; nt < 4; nt++)
                    b0[nt] = *(const uint2*)(bbase + ((nt * 32 + ks + 2) * 32 + lane) * 2);
            }
            // odd half (reuse a)
            #pragma unroll
            for (int mt = 0; mt < 4; mt++)
                a[mt] = *(const uint4*)(sA + ((mt * 32 + ks + 1) * 32 + lane) * 4);
            #pragma unroll
            for (int mt = 0; mt < 4; mt++)
                #pragma unroll
                for (int nt = 0; nt < 4; nt++)
                    mma16(acc2[mt][nt], a[mt], b1f[nt]);
            if (ks < 30) {
                #pragma unroll
                for (int nt = 0; nt < 4; nt++)
                    b1f[nt] = *(const uint2*)(bbase + ((nt * 32 + ks + 3) * 32 + lane) * 2);
            }
        }
    }

    // ---- epilogue: + b2, store ----
    #pragma unroll
    for (int mt = 0; mt < 4; mt++) {
        #pragma unroll
        for (int nt = 0; nt < 4; nt++) {
            int n  = warp * 32 + nt * 8 + 2 * tig;
            float bx = s_b2[n], by = s_b2[n + 1];
            int r0 = mt * 16 + gid;
            int e0 = base + r0;
            if (e0 < E) {
                float2 o;
                o.x = acc2[mt][nt][0] + bx;
                o.y = acc2[mt][nt][1] + by;
                *(float2*)(out + (size_t)e0 * 256 + n) = o;
            }
            int e1 = base + r0 + 8;
            if (e1 < E) {
                float2 o;
                o.x = acc2[mt][nt][2] + bx;
                o.y = acc2[mt][nt][3] + by;
                *(float2*)(out + (size_t)e1 * 256 + n) = o;
            }
        }
    }
}

// ------------------------------- launch ------------------------------------

extern "C" void kernel_launch(void* const* d_in, const int* in_sizes, int n_in,
                              void* d_out, int out_size) {
    const int*   src_nodes     = (const int*)d_in[0];
    const int*   dst_nodes     = (const int*)d_in[1];
    const float* timestamps    = (const float*)d_in[2];
    const int*   event_indices = (const int*)d_in[3];
    const int*   nidx          = (const int*)d_in[4];
    const float* node_emb      = (const float*)d_in[5];
    const float* last_update   = (const float*)d_in[6];
    const float* feats         = (const float*)d_in[7];
    const float* freq          = (const float*)d_in[8];
    const float* phase         = (const float*)d_in[9];
    const float* W1            = (const float*)d_in[10];
    const float* b1v           = (const float*)d_in[11];
    const float* W2            = (const float*)d_in[12];
    const float* b2v           = (const float*)d_in[13];
    float* out = (float*)d_out;

    int E = in_sizes[0];

    cudaFuncSetAttribute(tgn_msg_kernel,
                         cudaFuncAttributeMaxDynamicSharedMemorySize, SMEM_BYTES);

    prep_weights_kernel<<<128, 256>>>(W1, W2);

    int nblk = (E + E_TILE - 1) / E_TILE;
    tgn_msg_kernel<<<nblk, THREADS, SMEM_BYTES>>>(
        src_nodes, dst_nodes, timestamps, event_indices, nidx,
        node_emb, last_update, feats, freq, phase, b1v, b2v, out, E);
}

// round 16
// speedup vs baseline: 1.9450x; 1.0492x over previous
#include <cuda_runtime.h>
#include <cuda_fp16.h>
#include <cstdint>

// ---------------------------------------------------------------------------
// EmbedderMessageFunction (TGN message): fused gather + time-encode +
// MLP(512 -> relu 512 -> 256), FP16 mma.sync (m16n8k16, fp32 accum).
// R16: 512 threads / 16 warps (4 per SMSP) with halved per-warp N-slices
//      (GEMM1: 32, GEMM2: 16) to double scheduler occupancy.
// ---------------------------------------------------------------------------

#define E_TILE   64
#define THREADS  512

// smem layout (bytes)
#define OFF_A     0            // A fp16 fragments: 4 mt * 32 ks * 32 lanes * 16B = 65536
#define OFF_SA    65536        // staging A: 64 x 136 fp32 = 34816
#define OFF_SB    100352       // staging B: 64 x 136 fp32 = 34816
#define OFF_B1    135168       // 512 floats
#define OFF_B2    137216       // 256 floats
#define OFF_FREQ  138240       // 128 floats
#define OFF_PHASE 138752       // 128 floats
#define OFF_DT    139264       // 64 floats
#define OFF_SRC   139520       // 64 ints
#define OFF_DST   139776
#define OFF_EID   140032
#define SMEM_BYTES 140288

#define STAG_PITCH 136         // floats; 544B rows keep 16B cp.async alignment

// fp16x2-packed B-fragment weights (built once per launch by prep kernel).
// W1H: [ntg 0..63][ks16 0..31][lane 0..31][2] uint32   (HIDDEN=512)
// W2H: [ntg 0..31][ks16 0..31][lane 0..31][2] uint32   (OUT=256)
__device__ uint32_t g_W1H[64 * 32 * 32 * 2];
__device__ uint32_t g_W2H[32 * 32 * 32 * 2];

// pack two fp32 -> fp16x2 (lo in low 16 bits)
static __device__ __forceinline__ uint32_t packh2(float lo, float hi) {
    uint32_t r;
    asm("cvt.rn.f16x2.f32 %0, %1, %2;" : "=r"(r) : "f"(hi), "f"(lo));
    return r;
}

static __device__ __forceinline__ uint32_t smem_u32(const void* p) {
    uint32_t a;
    asm("{ .reg .u64 t; cvta.to.shared.u64 t, %1; cvt.u32.u64 %0, t; }"
        : "=r"(a) : "l"(p));
    return a;
}

static __device__ __forceinline__ void cp16(uint32_t dst, const void* src) {
    asm volatile("cp.async.cg.shared.global [%0], [%1], 16;"
                 :: "r"(dst), "l"(src) : "memory");
}
#define CP_COMMIT() asm volatile("cp.async.commit_group;" ::: "memory")
#define CP_WAIT(n)  asm volatile("cp.async.wait_group %0;" :: "n"(n) : "memory")

static __device__ __forceinline__ void mma16(float* d, uint4 a, uint2 b) {
    asm volatile(
        "mma.sync.aligned.m16n8k16.row.col.f32.f16.f16.f32 "
        "{%0,%1,%2,%3}, {%4,%5,%6,%7}, {%8,%9}, {%0,%1,%2,%3};"
        : "+f"(d[0]), "+f"(d[1]), "+f"(d[2]), "+f"(d[3])
        : "r"(a.x), "r"(a.y), "r"(a.z), "r"(a.w),
          "r"(b.x), "r"(b.y));
}

// ---------------------------- prep kernel ----------------------------------
// B fragment layout for mma.m16n8k16.row.col (fp16):
//   b0 = fp16x2{ W[k0+2tig][n], W[k0+2tig+1][n] }
//   b1 = fp16x2{ W[k0+8+2tig][n], W[k0+9+2tig][n] }   (n = ntg*8 + lane/4)

__global__ void prep_weights_kernel(const float* __restrict__ W1,
                                    const float* __restrict__ W2) {
    int t0 = blockIdx.x * blockDim.x + threadIdx.x;
    int stride = gridDim.x * blockDim.x;
    for (int t = t0; t < 64 * 32 * 32; t += stride) {
        int lane = t & 31, ks = (t >> 5) & 31, ntg = t >> 10;
        int tig = lane & 3, cg = lane >> 2;
        int k0 = ks * 16, n = ntg * 8 + cg;
        g_W1H[2 * t]     = packh2(W1[(size_t)(k0 + 2 * tig) * 512 + n],
                                  W1[(size_t)(k0 + 2 * tig + 1) * 512 + n]);
        g_W1H[2 * t + 1] = packh2(W1[(size_t)(k0 + 8 + 2 * tig) * 512 + n],
                                  W1[(size_t)(k0 + 9 + 2 * tig) * 512 + n]);
    }
    for (int t = t0; t < 32 * 32 * 32; t += stride) {
        int lane = t & 31, ks = (t >> 5) & 31, ntg = t >> 10;
        int tig = lane & 3, cg = lane >> 2;
        int k0 = ks * 16, n = ntg * 8 + cg;
        g_W2H[2 * t]     = packh2(W2[(size_t)(k0 + 2 * tig) * 256 + n],
                                  W2[(size_t)(k0 + 2 * tig + 1) * 256 + n]);
        g_W2H[2 * t + 1] = packh2(W2[(size_t)(k0 + 8 + 2 * tig) * 256 + n],
                                  W2[(size_t)(k0 + 9 + 2 * tig) * 256 + n]);
    }
}

// ----------------------------- main kernel ---------------------------------

__global__ __launch_bounds__(THREADS, 1)
void tgn_msg_kernel(const int*   __restrict__ src_nodes,
                    const int*   __restrict__ dst_nodes,
                    const float* __restrict__ timestamps,
                    const int*   __restrict__ event_indices,
                    const int*   __restrict__ nidx,
                    const float* __restrict__ node_emb,
                    const float* __restrict__ last_update,
                    const float* __restrict__ feats,
                    const float* __restrict__ freq,
                    const float* __restrict__ phase,
                    const float* __restrict__ b1,
                    const float* __restrict__ b2,
                    float*       __restrict__ out,
                    int E) {
    extern __shared__ char smem[];
    uint32_t* sA  = (uint32_t*)(smem + OFF_A);   // fp16x2 words
    float* stagA  = (float*)(smem + OFF_SA);
    float* stagB  = (float*)(smem + OFF_SB);
    float* s_b1   = (float*)(smem + OFF_B1);
    float* s_b2   = (float*)(smem + OFF_B2);
    float* s_frq  = (float*)(smem + OFF_FREQ);
    float* s_phs  = (float*)(smem + OFF_PHASE);
    float* s_dt   = (float*)(smem + OFF_DT);
    int*   s_src  = (int*)(smem + OFF_SRC);
    int*   s_dst  = (int*)(smem + OFF_DST);
    int*   s_eid  = (int*)(smem + OFF_EID);

    const uint32_t sbA = smem_u32(stagA);
    const uint32_t sbB = smem_u32(stagB);

    const int tid  = threadIdx.x;
    const int warp = tid >> 5;    // 0..15
    const int lane = tid & 31;
    const int gid  = lane >> 2;   // group id (row within fragment)
    const int tig  = lane & 3;    // thread in group

    const int base = blockIdx.x * E_TILE;

    // ---- preamble: indices / scalars into smem ----
    if (tid < E_TILE) {
        int e = base + tid;
        if (e >= E) e = E - 1;
        s_src[tid] = src_nodes[e];
        s_dst[tid] = dst_nodes[e];
        s_eid[tid] = event_indices[e];
        s_dt[tid]  = timestamps[e] - last_update[nidx[e]];
    }
    if (tid < 128) { s_frq[tid] = freq[tid]; s_phs[tid] = phase[tid]; }
    if (tid < 512) s_b1[tid] = b1[tid];
    if (tid < 256) s_b2[tid] = b2[tid];
    __syncthreads();

    // ---- async gather issue: src -> stagA (G0), dst -> stagB (G1) ----
    #pragma unroll
    for (int i = 0; i < 4; i++) {
        int lin = i * 512 + tid;
        int row = lin >> 5;
        int q   = lin & 31;
        cp16(sbA + (row * STAG_PITCH + q * 4) * 4,
             node_emb + (size_t)s_src[row] * 128 + q * 4);
    }
    CP_COMMIT();   // G0
    #pragma unroll
    for (int i = 0; i < 4; i++) {
        int lin = i * 512 + tid;
        int row = lin >> 5;
        int q   = lin & 31;
        cp16(sbB + (row * STAG_PITCH + q * 4) * 4,
             node_emb + (size_t)s_dst[row] * 128 + q * 4);
    }
    CP_COMMIT();   // G1

    // ---- chunk 2 (time encoding): cos directly into fp16 A fragments ----
    // chunk 2 covers k-steps 16..23 (cols 256..383 of msg).
    #pragma unroll
    for (int i = 0; i < 2; i++) {
        int f   = i * 16 + warp;      // fragment 0..31 of this chunk
        int mt  = f >> 3;             // m-tile 0..3
        int ksl = f & 7;              // local kstep16 0..7
        int ra = mt * 16 + gid;
        int ca = ksl * 16 + 2 * tig;  // time-dim col 0..127
        float dt0 = s_dt[ra], dt1 = s_dt[ra + 8];
        uint4 u;
        u.x = packh2(cosf(__fmaf_rn(dt0, s_frq[ca],     s_phs[ca])),
                     cosf(__fmaf_rn(dt0, s_frq[ca + 1], s_phs[ca + 1])));
        u.y = packh2(cosf(__fmaf_rn(dt1, s_frq[ca],     s_phs[ca])),
                     cosf(__fmaf_rn(dt1, s_frq[ca + 1], s_phs[ca + 1])));
        u.z = packh2(cosf(__fmaf_rn(dt0, s_frq[ca + 8], s_phs[ca + 8])),
                     cosf(__fmaf_rn(dt0, s_frq[ca + 9], s_phs[ca + 9])));
        u.w = packh2(cosf(__fmaf_rn(dt1, s_frq[ca + 8], s_phs[ca + 8])),
                     cosf(__fmaf_rn(dt1, s_frq[ca + 9], s_phs[ca + 9])));
        *(uint4*)(sA + ((mt * 32 + 16 + ksl) * 32 + lane) * 4) = u;
    }

    // ---- repack helper: staging fp32 -> fp16 A fragments for one chunk ----
    auto repack = [&](float* stag, int chunk) {
        #pragma unroll
        for (int i = 0; i < 2; i++) {
            int f   = i * 16 + warp;
            int mt  = f >> 3;
            int ksl = f & 7;
            int ra = mt * 16 + gid;
            int ca = ksl * 16 + 2 * tig;
            uint4 u;
            u.x = packh2(stag[ra * STAG_PITCH + ca],
                         stag[ra * STAG_PITCH + ca + 1]);
            u.y = packh2(stag[(ra + 8) * STAG_PITCH + ca],
                         stag[(ra + 8) * STAG_PITCH + ca + 1]);
            u.z = packh2(stag[ra * STAG_PITCH + ca + 8],
                         stag[ra * STAG_PITCH + ca + 9]);
            u.w = packh2(stag[(ra + 8) * STAG_PITCH + ca + 8],
                         stag[(ra + 8) * STAG_PITCH + ca + 9]);
            *(uint4*)(sA + ((mt * 32 + chunk * 8 + ksl) * 32 + lane) * 4) = u;
        }
    };

    CP_WAIT(1);          // G0 (src) landed
    __syncthreads();
    repack(stagA, 0);    // src -> k-steps 0..7
    __syncthreads();     // stagA free

    // ---- feats -> stagA (G2) ----
    #pragma unroll
    for (int i = 0; i < 4; i++) {
        int lin = i * 512 + tid;
        int row = lin >> 5;
        int q   = lin & 31;
        cp16(sbA + (row * STAG_PITCH + q * 4) * 4,
             feats + (size_t)s_eid[row] * 128 + q * 4);
    }
    CP_COMMIT();   // G2

    CP_WAIT(1);          // G1 (dst) landed (G2 may be pending)
    __syncthreads();
    repack(stagB, 1);    // dst -> k-steps 8..15

    CP_WAIT(0);          // G2 (feats) landed
    __syncthreads();
    repack(stagA, 3);    // feats -> k-steps 24..31
    __syncthreads();

    // ---- GEMM1: h[64x512] = msg @ W1 ; N-slice 32 per warp, 32 k16-steps ----
    float acc[4][4][4];
    #pragma unroll
    for (int mt = 0; mt < 4; mt++)
        #pragma unroll
        for (int nt = 0; nt < 4; nt++)
            #pragma unroll
            for (int r = 0; r < 4; r++) acc[mt][nt][r] = 0.0f;

    {
        const uint32_t* bbase = g_W1H + (size_t)(warp * 4) * 2048; // 4 ntg * (32 ks * 64)
        uint2 b0[4], b1f[4];
        #pragma unroll
        for (int nt = 0; nt < 4; nt++) {
            b0[nt]  = *(const uint2*)(bbase + ((nt * 32 + 0) * 32 + lane) * 2);
            b1f[nt] = *(const uint2*)(bbase + ((nt * 32 + 1) * 32 + lane) * 2);
        }
        #pragma unroll 1
        for (int ks = 0; ks < 32; ks += 2) {
            uint4 a[4];
            // even half
            #pragma unroll
            for (int mt = 0; mt < 4; mt++)
                a[mt] = *(const uint4*)(sA + ((mt * 32 + ks) * 32 + lane) * 4);
            #pragma unroll
            for (int mt = 0; mt < 4; mt++)
                #pragma unroll
                for (int nt = 0; nt < 4; nt++)
                    mma16(acc[mt][nt], a[mt], b0[nt]);
            if (ks < 30) {
                #pragma unroll
                for (int nt = 0; nt < 4; nt++)
                    b0[nt] = *(const uint2*)(bbase + ((nt * 32 + ks + 2) * 32 + lane) * 2);
            }
            // odd half (reuse a)
            #pragma unroll
            for (int mt = 0; mt < 4; mt++)
                a[mt] = *(const uint4*)(sA + ((mt * 32 + ks + 1) * 32 + lane) * 4);
            #pragma unroll
            for (int mt = 0; mt < 4; mt++)
                #pragma unroll
                for (int nt = 0; nt < 4; nt++)
                    mma16(acc[mt][nt], a[mt], b1f[nt]);
            if (ks < 30) {
                #pragma unroll
                for (int nt = 0; nt < 4; nt++)
                    b1f[nt] = *(const uint2*)(bbase + ((nt * 32 + ks + 3) * 32 + lane) * 2);
            }
        }
    }

    // ---- relu + b1: write h as fp16 A fragments for GEMM2 (in place) ----
    // h col n = warp*32 + nt*8 + 2tig(+1) -> ks2 = warp*2 + (nt>>1),
    // word offset 2*(nt&1); writer lane owns its own fragment slot.
    __syncthreads();   // everyone done reading msg A
    #pragma unroll
    for (int mt = 0; mt < 4; mt++) {
        #pragma unroll
        for (int nt = 0; nt < 4; nt++) {
            int n_even = warp * 32 + nt * 8 + 2 * tig;
            int ks2 = warp * 2 + (nt >> 1);
            uint32_t* dst = sA + ((mt * 32 + ks2) * 32 + lane) * 4 + 2 * (nt & 1);
            float v0 = fmaxf(acc[mt][nt][0] + s_b1[n_even],     0.0f);
            float v1 = fmaxf(acc[mt][nt][1] + s_b1[n_even + 1], 0.0f);
            float v2 = fmaxf(acc[mt][nt][2] + s_b1[n_even],     0.0f);
            float v3 = fmaxf(acc[mt][nt][3] + s_b1[n_even + 1], 0.0f);
            dst[0] = packh2(v0, v1);   // row gid
            dst[1] = packh2(v2, v3);   // row gid+8
        }
    }
    __syncthreads();

    // ---- GEMM2: out[64x256] = h @ W2 ; N-slice 16 per warp, 32 k16-steps ----
    float acc2[4][2][4];
    #pragma unroll
    for (int mt = 0; mt < 4; mt++)
        #pragma unroll
        for (int nt = 0; nt < 2; nt++)
            #pragma unroll
            for (int r = 0; r < 4; r++) acc2[mt][nt][r] = 0.0f;

    {
        const uint32_t* bbase = g_W2H + (size_t)(warp * 2) * 2048;
        uint2 b0[2], b1f[2];
        #pragma unroll
        for (int nt = 0; nt < 2; nt++) {
            b0[nt]  = *(const uint2*)(bbase + ((nt * 32 + 0) * 32 + lane) * 2);
            b1f[nt] = *(const uint2*)(bbase + ((nt * 32 + 1) * 32 + lane) * 2);
        }
        #pragma unroll 1
        for (int ks = 0; ks < 32; ks += 2) {
            uint4 a[4];
            // even half
            #pragma unroll
            for (int mt = 0; mt < 4; mt++)
                a[mt] = *(const uint4*)(sA + ((mt * 32 + ks) * 32 + lane) * 4);
            #pragma unroll
            for (int mt = 0; mt < 4; mt++)
                #pragma unroll
                for (int nt = 0; nt < 2; nt++)
                    mma16(acc2[mt][nt], a[mt], b0[nt]);
            if (ks < 30) {
                #pragma unroll
                for (int nt = 0; nt < 2; nt++)
                    b0[nt] = *(const uint2*)(bbase + ((nt * 32 + ks + 2) * 32 + lane) * 2);
            }
            // odd half (reuse a)
            #pragma unroll
            for (int mt = 0; mt < 4; mt++)
                a[mt] = *(const uint4*)(sA + ((mt * 32 + ks + 1) * 32 + lane) * 4);
            #pragma unroll
            for (int mt = 0; mt < 4; mt++)
                #pragma unroll
                for (int nt = 0; nt < 2; nt++)
                    mma16(acc2[mt][nt], a[mt], b1f[nt]);
            if (ks < 30) {
                #pragma unroll
                for (int nt = 0; nt < 2; nt++)
                    b1f[nt] = *(const uint2*)(bbase + ((nt * 32 + ks + 3) * 32 + lane) * 2);
            }
        }
    }

    // ---- epilogue: + b2, store ----
    #pragma unroll
    for (int mt = 0; mt < 4; mt++) {
        #pragma unroll
        for (int nt = 0; nt < 2; nt++) {
            int n  = warp * 16 + nt * 8 + 2 * tig;
            float bx = s_b2[n], by = s_b2[n + 1];
            int r0 = mt * 16 + gid;
            int e0 = base + r0;
            if (e0 < E) {
                float2 o;
                o.x = acc2[mt][nt][0] + bx;
                o.y = acc2[mt][nt][1] + by;
                *(float2*)(out + (size_t)e0 * 256 + n) = o;
            }
            int e1 = base + r0 + 8;
            if (e1 < E) {
                float2 o;
                o.x = acc2[mt][nt][2] + bx;
                o.y = acc2[mt][nt][3] + by;
                *(float2*)(out + (size_t)e1 * 256 + n) = o;
            }
        }
    }
}

// ------------------------------- launch ------------------------------------

extern "C" void kernel_launch(void* const* d_in, const int* in_sizes, int n_in,
                              void* d_out, int out_size) {
    const int*   src_nodes     = (const int*)d_in[0];
    const int*   dst_nodes     = (const int*)d_in[1];
    const float* timestamps    = (const float*)d_in[2];
    const int*   event_indices = (const int*)d_in[3];
    const int*   nidx          = (const int*)d_in[4];
    const float* node_emb      = (const float*)d_in[5];
    const float* last_update   = (const float*)d_in[6];
    const float* feats         = (const float*)d_in[7];
    const float* freq          = (const float*)d_in[8];
    const float* phase         = (const float*)d_in[9];
    const float* W1            = (const float*)d_in[10];
    const float* b1v           = (const float*)d_in[11];
    const float* W2            = (const float*)d_in[12];
    const float* b2v           = (const float*)d_in[13];
    float* out = (float*)d_out;

    int E = in_sizes[0];

    cudaFuncSetAttribute(tgn_msg_kernel,
                         cudaFuncAttributeMaxDynamicSharedMemorySize, SMEM_BYTES);

    prep_weights_kernel<<<128, 256>>>(W1, W2);

    int nblk = (E + E_TILE - 1) / E_TILE;
    tgn_msg_kernel<<<nblk, THREADS, SMEM_BYTES>>>(
        src_nodes, dst_nodes, timestamps, event_indices, nidx,
        node_emb, last_update, feats, freq, phase, b1v, b2v, out, E);
}